// round 17
// baseline (speedup 1.0000x reference)
#include <cuda_runtime.h>
#include <cuda_fp16.h>
#include <cstdint>

#define NB 256
#define TT 128
#define DD 1024
#define HH 1024
#define LL 49
#define K3 3072
#define N4 4096

typedef __half hf;

// ---------------- scratch (static device globals; no runtime allocation) ----------------
// W columns are PERMUTED: c_new = 4*j + gate  (gate = c_old/1024, j = c_old%1024).
// Hence P0/P1 and Z are stored in permuted column space too.
__device__ __align__(256) hf    g_X16[TT * NB * DD];   // x fp16, [t][n][k]
__device__ __align__(256) hf    g_A16[NB * HH * LL];   // A fp16 (attention only)
__device__ __align__(256) hf    g_W16[N4 * K3];        // W concat transposed [c_new][k], fp16
__device__ __align__(256) float g_c[NB * HH];
__device__ __align__(256) hf    g_h16[NB * HH];
__device__ __align__(256) hf    g_a16[NB * HH];        // attn fp16
__device__ __align__(256) hf    g_P0[NB * N4];         // h-slice partial z=0 (fp16, permuted cols)
__device__ __align__(256) hf    g_P1[NB * N4];         // h-slice partial z=1
__device__ __align__(256) hf    g_Z16[(size_t)TT * NB * N4];  // x@Wx all t (fp16, permuted cols)

__device__ __forceinline__ void cp16(const void* smem_dst, const void* gsrc) {
    unsigned s = (unsigned)__cvta_generic_to_shared((void*)smem_dst);
    asm volatile("cp.async.cg.shared.global [%0], [%1], 16;\n" :: "r"(s), "l"(gsrc));
}
__device__ __forceinline__ void cp16_ll(const void* smem_dst, const void* gsrc, uint64_t pol) {
    unsigned s = (unsigned)__cvta_generic_to_shared((void*)smem_dst);
    asm volatile("cp.async.cg.shared.global.L2::cache_hint [%0], [%1], 16, %2;\n"
                 :: "r"(s), "l"(gsrc), "l"(pol));
}
__device__ __forceinline__ uint64_t mkpol_evict_last() {
    uint64_t pol;
    asm("createpolicy.fractional.L2::evict_last.b64 %0, 1.0;" : "=l"(pol));
    return pol;
}

__device__ __forceinline__ void mma16816(float* d, const unsigned* a, const unsigned* b) {
    asm volatile(
        "mma.sync.aligned.m16n8k16.row.col.f32.f16.f16.f32 "
        "{%0,%1,%2,%3}, {%4,%5,%6,%7}, {%8,%9}, {%0,%1,%2,%3};\n"
        : "+f"(d[0]), "+f"(d[1]), "+f"(d[2]), "+f"(d[3])
        : "r"(a[0]), "r"(a[1]), "r"(a[2]), "r"(a[3]), "r"(b[0]), "r"(b[1]));
}

__device__ __forceinline__ void ldsm_x4(unsigned* r, unsigned addr) {
    asm volatile("ldmatrix.sync.aligned.m8n8.x4.shared.b16 {%0,%1,%2,%3}, [%4];"
                 : "=r"(r[0]), "=r"(r[1]), "=r"(r[2]), "=r"(r[3]) : "r"(addr));
}
__device__ __forceinline__ void ldsm_x2(unsigned* r, unsigned addr) {
    asm volatile("ldmatrix.sync.aligned.m8n8.x2.shared.b16 {%0,%1}, [%2];"
                 : "=r"(r[0]), "=r"(r[1]) : "r"(addr));
}

__device__ __forceinline__ void load4h(const hf* p, float& x0, float& x1, float& x2, float& x3) {
    __half2 a = *(const __half2*)p;
    __half2 b = *(const __half2*)(p + 2);
    x0 = __low2float(a); x1 = __high2float(a);
    x2 = __low2float(b); x3 = __high2float(b);
}

// ---------------- prep kernels ----------------
__global__ void __launch_bounds__(256) k_prepX(const float* __restrict__ x) {
    int idx = blockIdx.x * 256 + threadIdx.x;     // over T*N*D, x is (N,T,D)
    int k = idx & 1023;
    int r = idx >> 10;                            // n*TT + t
    int t = r & 127;
    int n = r >> 7;
    g_X16[(t * NB + n) * DD + k] = __float2half(x[idx]);
}

__global__ void __launch_bounds__(256) k_prepA(const float* __restrict__ A) {
    int idx = blockIdx.x * 256 + threadIdx.x;
    g_A16[idx] = __float2half(A[idx]);
}

__global__ void k_prepW(const float* __restrict__ Wx, const float* __restrict__ Wh,
                        const float* __restrict__ Wattn) {
    __shared__ float tile[32][33];
    int k0 = blockIdx.x * 32, n0 = blockIdx.y * 32;
    int tx = threadIdx.x, ty = threadIdx.y;       // block (32,8)
    const float* src; int kb;
    if (k0 < 1024)      { src = Wx;    kb = 0; }
    else if (k0 < 2048) { src = Wh;    kb = 1024; }
    else                { src = Wattn; kb = 2048; }
    #pragma unroll
    for (int i = 0; i < 4; ++i) {
        int r = ty + i * 8;
        tile[r][tx] = src[(k0 - kb + r) * N4 + n0 + tx];
    }
    __syncthreads();
    #pragma unroll
    for (int i = 0; i < 4; ++i) {
        int r = ty + i * 8;
        int n = n0 + r, k = k0 + tx;
        int np = 4 * (n & 1023) + (n >> 10);      // gate-interleave permutation
        g_W16[np * K3 + k] = __float2half(tile[tx][r]);
    }
}

__global__ void __launch_bounds__(256) k_init(const float* __restrict__ A) {
    int idx = blockIdx.x * 256 + threadIdx.x;     // over NB*HH
    const float* Ap = A + (size_t)idx * LL;
    float s = 0.f;
    #pragma unroll
    for (int l = 0; l < LL; ++l) s += Ap[l];
    s *= (1.f / 49.f);
    g_c[idx] = s;
    g_h16[idx] = __float2half(s);
}

// ---------------- GEMM tile body (128x128, used by Z prep and h-slice) ----------------
#define SMS 5120   // 128*40 halfs per stage per matrix
#define NSTAGE 3

__device__ __forceinline__ void gemm_load_chunk(int kc, int buf, int bm, int bn, int tid,
                                                hf* sAd, hf* sBh) {
    const hf* pA; int kA;
    if (kc < 1024)      { pA = g_X16; kA = kc; }
    else                { pA = g_h16; kA = kc - 1024; }
    #pragma unroll
    for (int j = 0; j < 4; ++j) {
        int v = tid + 256 * j;        // 0..1023
        int mat = v >> 9;             // 0=A 1=B
        int rem = v & 511;
        int row = rem >> 2, cq = rem & 3;
        int soff = buf * SMS + row * 40 + cq * 8;
        if (mat == 0) {
            cp16(sAd + soff, pA + (bm * 128 + row) * 1024 + kA + cq * 8);
        } else {
            cp16(sBh + soff, g_W16 + (size_t)(bn * 128 + row) * K3 + kc + cq * 8);
        }
    }
    asm volatile("cp.async.commit_group;\n" ::);
}

template <bool TOZ>
__device__ __forceinline__ void gemm_tile(int kc0, int nchunks, int bm, int bn,
                                          hf* P, hf* sm) {
    hf* sAd = sm;
    hf* sBh = sm + NSTAGE * SMS;
    const int tid  = threadIdx.x;
    const int lane = tid & 31, w = tid >> 5;
    const int wm = w & 1, wn = w >> 1;          // 2x4 warp grid, warp tile 64x32
    const int lr = lane >> 2, lc = lane & 3;

    const unsigned bAd = (unsigned)__cvta_generic_to_shared(sAd);
    const unsigned bBh = (unsigned)__cvta_generic_to_shared(sBh);
    const unsigned aoff = (unsigned)((wm * 64 + (lane & 7) + ((lane >> 3) & 1) * 8) * 80
                                     + ((lane >> 4) & 1) * 16);
    const unsigned boff = (unsigned)((wn * 32 + (lane & 7)) * 80 + ((lane >> 3) & 1) * 16);

    float d[4][4][4];
    #pragma unroll
    for (int a = 0; a < 4; ++a)
        #pragma unroll
        for (int b2 = 0; b2 < 4; ++b2)
            #pragma unroll
            for (int c = 0; c < 4; ++c) d[a][b2][c] = 0.f;

    gemm_load_chunk(kc0,      0, bm, bn, tid, sAd, sBh);
    gemm_load_chunk(kc0 + 32, 1, bm, bn, tid, sAd, sBh);

    int cb = 0;
    int lb = 2;
    for (int it = 0; it < nchunks; ++it) {
        asm volatile("cp.async.wait_group 1;\n" ::);
        __syncthreads();
        if (it + 2 < nchunks) {
            gemm_load_chunk(kc0 + (it + 2) * 32, lb, bm, bn, tid, sAd, sBh);
            if (++lb == NSTAGE) lb = 0;
        }
        const unsigned cbo = (unsigned)(cb * SMS * 2);
        if (++cb == NSTAGE) cb = 0;
        #pragma unroll
        for (int kt = 0; kt < 32; kt += 16) {
            unsigned ad[4][4], bh[4][2];
            #pragma unroll
            for (int mt = 0; mt < 4; ++mt) {
                unsigned o = cbo + (unsigned)(mt * 1280 + kt * 2) + aoff;
                ldsm_x4(ad[mt], bAd + o);
            }
            #pragma unroll
            for (int nt = 0; nt < 4; ++nt) {
                unsigned o = cbo + (unsigned)(nt * 640 + kt * 2) + boff;
                ldsm_x2(bh[nt], bBh + o);
            }
            #pragma unroll
            for (int mt = 0; mt < 4; ++mt)
                #pragma unroll
                for (int nt = 0; nt < 4; ++nt)
                    mma16816(d[mt][nt], ad[mt], bh[nt]);
        }
        __syncthreads();
    }

    if (TOZ) {
        #pragma unroll
        for (int mt = 0; mt < 4; ++mt) {
            size_t r = (size_t)(bm * 128 + wm * 64 + mt * 16 + lr);
            #pragma unroll
            for (int nt = 0; nt < 4; ++nt) {
                int cN = bn * 128 + wn * 32 + nt * 8 + 2 * lc;
                __half2 v0 = __floats2half2_rn(d[mt][nt][0], d[mt][nt][1]);
                __half2 v1 = __floats2half2_rn(d[mt][nt][2], d[mt][nt][3]);
                *(__half2*)&g_Z16[r * N4 + cN]       = v0;
                *(__half2*)&g_Z16[(r + 8) * N4 + cN] = v1;
            }
        }
    } else {
        #pragma unroll
        for (int mt = 0; mt < 4; ++mt) {
            int r = bm * 128 + wm * 64 + mt * 16 + lr;
            #pragma unroll
            for (int nt = 0; nt < 4; ++nt) {
                int cN = bn * 128 + wn * 32 + nt * 8 + 2 * lc;
                __half2 v0 = __floats2half2_rn(d[mt][nt][0], d[mt][nt][1]);
                __half2 v1 = __floats2half2_rn(d[mt][nt][2], d[mt][nt][3]);
                *(__half2*)&P[r * N4 + cN]       = v0;
                *(__half2*)&P[(r + 8) * N4 + cN] = v1;
            }
        }
    }
}

// ---------------- attention body (256 threads) ----------------
#define ATT_CHUNKS ((HH * LL * 2) / 16)   // 6272 16B chunks
__device__ __forceinline__ void att_body(int n, hf* sA16) {
    const int tid = threadIdx.x;
    const int lane = tid & 31, wid = tid >> 5;
    __shared__ float sh[HH];
    __shared__ float sw[64];

    {
        const uint64_t pol = mkpol_evict_last();
        const uint4* Ap = (const uint4*)(g_A16 + (size_t)n * (HH * LL));
        uint4* dst = (uint4*)sA16;
        for (int i = tid; i < ATT_CHUNKS; i += 256)
            cp16_ll(dst + i, Ap + i, pol);
        asm volatile("cp.async.commit_group;\n" ::);
        for (int i = tid; i < HH; i += 256) sh[i] = __half2float(g_h16[n * HH + i]);
        asm volatile("cp.async.wait_group 0;\n" ::);
    }
    __syncthreads();

    for (int l = wid; l < LL; l += 8) {
        float acc = 0.f;
        #pragma unroll 8
        for (int h = lane; h < HH; h += 32)
            acc += __half2float(sA16[h * LL + l]) * sh[h];
        #pragma unroll
        for (int off = 16; off; off >>= 1)
            acc += __shfl_xor_sync(0xffffffffu, acc, off);
        if (lane == 0) sw[l] = acc * 0.03125f;    // 1/sqrt(H)
    }
    __syncthreads();

    if (wid == 0) {
        float v0 = (lane < LL) ? sw[lane] : -1e30f;
        float v1 = (lane + 32 < LL) ? sw[lane + 32] : -1e30f;
        float m = fmaxf(v0, v1);
        #pragma unroll
        for (int off = 16; off; off >>= 1)
            m = fmaxf(m, __shfl_xor_sync(0xffffffffu, m, off));
        float e0 = (lane < LL) ? __expf(v0 - m) : 0.f;
        float e1 = (lane + 32 < LL) ? __expf(v1 - m) : 0.f;
        float s = e0 + e1;
        #pragma unroll
        for (int off = 16; off; off >>= 1)
            s += __shfl_xor_sync(0xffffffffu, s, off);
        float inv = 1.f / s;
        if (lane < LL) sw[lane] = e0 * inv;
        if (lane + 32 < LL) sw[lane + 32] = e1 * inv;
    }
    __syncthreads();

    for (int h = tid; h < HH; h += 256) {
        const hf* row = sA16 + h * LL;
        float acc = 0.f;
        #pragma unroll
        for (int l = 0; l < LL; ++l) acc += sw[l] * __half2float(row[l]);
        g_a16[n * HH + h] = __float2half(acc);
    }
}

// ---------------- fused per-step kernel: h-GEMM (blocks 0..127) + attention (128..383) ----------------
__global__ void __launch_bounds__(256) k_fused() {
    extern __shared__ hf smu[];
    if (blockIdx.x < 128) {
        int bid = blockIdx.x;
        int bm = bid & 1, bn = (bid >> 1) & 31, z = bid >> 6;   // split-K=2 over h slice
        gemm_tile<false>(1024 + z * 512, 16, bm, bn, z ? g_P1 : g_P0, smu);
    } else {
        att_body(blockIdx.x - 128, smu);
    }
}

// ---------------- attn-slice GEMM with FUSED GATES: tile 128x64, grid (2,64), full K=1024 ----------------
#define SMS_B2 2560   // 64*40 halfs per stage for B

__device__ __forceinline__ void g2_load(int kc, int buf, int bm, int bn, int tid,
                                        hf* sAd, hf* sBh) {
    const int kA = kc - 2048;
    #pragma unroll
    for (int j = 0; j < 2; ++j) {
        int v = tid + 256 * j;        // 0..511 : A chunks
        int row = v >> 2, cq = v & 3;
        cp16(sAd + buf * SMS + row * 40 + cq * 8,
             g_a16 + (bm * 128 + row) * 1024 + kA + cq * 8);
    }
    {
        int row = tid >> 2, cq = tid & 3;   // 256 B chunks (64 rows x 4)
        cp16(sBh + buf * SMS_B2 + row * 40 + cq * 8,
             g_W16 + (size_t)(bn * 64 + row) * K3 + kc + cq * 8);
    }
    asm volatile("cp.async.commit_group;\n" ::);
}

__global__ void __launch_bounds__(256) k_gemmG(int t, const float* __restrict__ bvec,
                                               float* __restrict__ out) {
    extern __shared__ hf smu[];
    hf* sAd = smu;                       // 3 * 5120
    hf* sBh = smu + NSTAGE * SMS;        // 3 * 2560
    const int bm = blockIdx.x, bn = blockIdx.y;
    const int tid  = threadIdx.x;
    const int lane = tid & 31, w = tid >> 5;
    const int wm = w & 1, wn = w >> 1;   // 2x4 warps, warp tile 64x16
    const int lr = lane >> 2, lc = lane & 3;

    const unsigned bAd = (unsigned)__cvta_generic_to_shared(sAd);
    const unsigned bBh = (unsigned)__cvta_generic_to_shared(sBh);
    const unsigned aoff = (unsigned)((wm * 64 + (lane & 7) + ((lane >> 3) & 1) * 8) * 80
                                     + ((lane >> 4) & 1) * 16);
    const unsigned boff = (unsigned)((wn * 16 + (lane & 7)) * 80 + ((lane >> 3) & 1) * 16);

    float d[4][2][4];
    #pragma unroll
    for (int a = 0; a < 4; ++a)
        #pragma unroll
        for (int b2 = 0; b2 < 2; ++b2)
            #pragma unroll
            for (int c = 0; c < 4; ++c) d[a][b2][c] = 0.f;

    g2_load(2048,      0, bm, bn, tid, sAd, sBh);
    g2_load(2048 + 32, 1, bm, bn, tid, sAd, sBh);

    int cb = 0;
    int lb = 2;
    for (int it = 0; it < 32; ++it) {
        asm volatile("cp.async.wait_group 1;\n" ::);
        __syncthreads();
        if (it + 2 < 32) {
            g2_load(2048 + (it + 2) * 32, lb, bm, bn, tid, sAd, sBh);
            if (++lb == NSTAGE) lb = 0;
        }
        const unsigned cboA = (unsigned)(cb * SMS * 2);
        const unsigned cboB = (unsigned)(cb * SMS_B2 * 2);
        if (++cb == NSTAGE) cb = 0;
        #pragma unroll
        for (int kt = 0; kt < 32; kt += 16) {
            unsigned ad[4][4], bh[2][2];
            #pragma unroll
            for (int mt = 0; mt < 4; ++mt) {
                unsigned o = cboA + (unsigned)(mt * 1280 + kt * 2) + aoff;
                ldsm_x4(ad[mt], bAd + o);
            }
            #pragma unroll
            for (int nt = 0; nt < 2; ++nt) {
                unsigned o = cboB + (unsigned)(nt * 640 + kt * 2) + boff;
                ldsm_x2(bh[nt], bBh + o);
            }
            #pragma unroll
            for (int mt = 0; mt < 4; ++mt)
                #pragma unroll
                for (int nt = 0; nt < 2; ++nt)
                    mma16816(d[mt][nt], ad[mt], bh[nt]);
        }
        __syncthreads();
    }

    // fused gate epilogue: permuted cols c = 4*j + gate.
    // even lane (lc bit0 = 0) handles row lr; odd lane row lr+8; lane^1 swap completes quads.
    const int odd = lane & 1;
    const int lc2 = lc >> 1;
    const hf* Zt = g_Z16 + (size_t)t * NB * N4;
    #pragma unroll
    for (int mt = 0; mt < 4; ++mt) {
        int base_r = bm * 128 + wm * 64 + mt * 16 + lr;
        #pragma unroll
        for (int nt = 0; nt < 2; ++nt) {
            float p0 = __shfl_xor_sync(0xffffffffu, d[mt][nt][0], 1);
            float p1 = __shfl_xor_sync(0xffffffffu, d[mt][nt][1], 1);
            float p2 = __shfl_xor_sync(0xffffffffu, d[mt][nt][2], 1);
            float p3 = __shfl_xor_sync(0xffffffffu, d[mt][nt][3], 1);
            float a0, a1, a2, a3;
            int n;
            if (!odd) { a0 = d[mt][nt][0]; a1 = d[mt][nt][1]; a2 = p0; a3 = p1; n = base_r; }
            else      { a0 = p2; a1 = p3; a2 = d[mt][nt][2]; a3 = d[mt][nt][3]; n = base_r + 8; }
            int j = bn * 16 + wn * 4 + nt * 2 + lc2;
            size_t pc = (size_t)n * N4 + 4 * j;
            float q0, q1, q2, q3;
            load4h(g_P0 + pc, q0, q1, q2, q3);
            a0 += q0; a1 += q1; a2 += q2; a3 += q3;
            load4h(g_P1 + pc, q0, q1, q2, q3);
            a0 += q0; a1 += q1; a2 += q2; a3 += q3;
            load4h(Zt + pc, q0, q1, q2, q3);
            a0 += q0; a1 += q1; a2 += q2; a3 += q3;
            a0 += bvec[j];
            a1 += bvec[j + 1024];
            a2 += bvec[j + 2048];
            a3 += bvec[j + 3072];
            float ig = 1.f / (1.f + expf(-a0));
            float fg = 1.f / (1.f + expf(-a1));
            float og = 1.f / (1.f + expf(-a2));
            float gg = tanhf(a3);
            int hidx = n * HH + j;
            float c = fg * g_c[hidx] + ig * gg;
            g_c[hidx] = c;
            float hn = og * tanhf(c);
            out[(n * TT + t) * HH + j] = hn;
            g_h16[hidx] = __float2half(hn);
        }
    }
}

// ---------------- prep GEMM: Z = X @ Wx for all t ----------------
__global__ void __launch_bounds__(256) k_gemmZ() {
    extern __shared__ hf smu[];
    gemm_tile<true>(0, 32, blockIdx.x, blockIdx.y, nullptr, smu);
}

// ---------------- launch ----------------
extern "C" void kernel_launch(void* const* d_in, const int* in_sizes, int n_in,
                              void* d_out, int out_size) {
    (void)in_sizes; (void)n_in; (void)out_size;
    const float* x     = (const float*)d_in[0];
    const float* A     = (const float*)d_in[1];
    const float* Wx    = (const float*)d_in[2];
    const float* Wh    = (const float*)d_in[3];
    const float* Wattn = (const float*)d_in[4];
    const float* bvec  = (const float*)d_in[5];
    float* out = (float*)d_out;

    const int gemmSmem  = 2 * NSTAGE * SMS * (int)sizeof(hf);            // 61440
    const int gemm2Smem = NSTAGE * (SMS + SMS_B2) * (int)sizeof(hf);     // 46080
    const int attSmem   = HH * LL * (int)sizeof(hf);                     // 100352
    cudaFuncSetAttribute(k_gemmZ, cudaFuncAttributeMaxDynamicSharedMemorySize, gemmSmem);
    cudaFuncSetAttribute(k_gemmG, cudaFuncAttributeMaxDynamicSharedMemorySize, gemm2Smem);
    cudaFuncSetAttribute(k_fused, cudaFuncAttributeMaxDynamicSharedMemorySize, attSmem);

    // prep
    k_prepX<<<(TT * NB * DD) / 256, 256>>>(x);
    k_prepA<<<(NB * HH * LL) / 256, 256>>>(A);
    k_prepW<<<dim3(K3 / 32, N4 / 32), dim3(32, 8)>>>(Wx, Wh, Wattn);
    k_init<<<(NB * HH) / 256, 256>>>(A);

    // one big batched GEMM: Z[t] = x_t @ Wx for ALL t (permuted cols)
    k_gemmZ<<<dim3(TT * NB / 128, 32), 256, gemmSmem>>>();

    for (int t = 0; t < TT; ++t) {
        k_fused<<<384, 256, attSmem>>>();                       // h-GEMM || attention
        k_gemmG<<<dim3(2, 64), 256, gemm2Smem>>>(t, bvec, out); // attn GEMM + gates
    }
}